// round 1
// baseline (speedup 1.0000x reference)
#include <cuda_runtime.h>

// Problem constants (fixed by the dataset):
//   x: (4,1,128,2048) f32 ; vals: 16.7M f32 ; rows/cols: 16.7M int64-or-int32 (sorted rows)
//   out: (4,1,512,256) f32 = 524288 elements
#define NNZ_TOTAL   16777216
#define NCOLS       262144      // NS*NC = 2048*128
#define NROWS       131072      // NX*NZ = 256*512
#define OUT_PLANE   131072      // per-bk output plane
#define TOTAL_WARPS 8192
#define NNZ_PER_WARP (NNZ_TOTAL / TOTAL_WARPS)   // 2048
#define ITERS        (NNZ_PER_WARP / 32)         // 64

// Scratch: transposed RHS, rhs_t[col] = {x[0,c,s], x[1,c,s], x[2,c,s], x[3,c,s]}, col = s*128 + c
static __device__ float4  g_rhs[NCOLS];          // 4 MB, L2-resident during main kernel
static __device__ unsigned g_stride;             // 2 if indices are int64, 1 if int32

// --- dtype probe -------------------------------------------------------------
// Word [NNZ-1] (u32 view) is in-bounds for both layouts:
//   int64: it is the HIGH half of element (NNZ-2)/2  -> always 0 (values < 2^31)
//   int32: it is the LAST (max, sorted) row value    -> ~131071, nonzero w.p. ~1
__global__ void k_config(const unsigned* __restrict__ rows_u32) {
    g_stride = (rows_u32[NNZ_TOTAL - 1] == 0u) ? 2u : 1u;
}

// --- zero output (d_out is poisoned 0xAA) ------------------------------------
__global__ void k_zero(float* __restrict__ out) {
    out[blockIdx.x * blockDim.x + threadIdx.x] = 0.0f;
}

// --- build transposed RHS -----------------------------------------------------
__global__ void k_build_rhs(const float* __restrict__ x) {
    unsigned col = blockIdx.x * blockDim.x + threadIdx.x;   // < 262144
    unsigned c = col & 127u;
    unsigned s = col >> 7;
    unsigned o = c * 2048u + s;
    float4 v;
    v.x = x[o];
    v.y = x[o + 262144u];
    v.z = x[o + 524288u];
    v.w = x[o + 786432u];
    g_rhs[col] = v;
}

// --- flush one completed row: butterfly reduce across warp, 4 atomics ---------
__device__ __forceinline__ void flush_row(unsigned row,
                                          float a0, float a1, float a2, float a3,
                                          float* __restrict__ out) {
    #pragma unroll
    for (int d = 16; d > 0; d >>= 1) {
        a0 += __shfl_xor_sync(0xffffffffu, a0, d);
        a1 += __shfl_xor_sync(0xffffffffu, a1, d);
        a2 += __shfl_xor_sync(0xffffffffu, a2, d);
        a3 += __shfl_xor_sync(0xffffffffu, a3, d);
    }
    unsigned lane = threadIdx.x & 31u;
    if (lane < 4u) {
        float v = (lane == 0u) ? a0 : (lane == 1u) ? a1 : (lane == 2u) ? a2 : a3;
        // out layout: bk*131072 + z*256 + x, with row r = x*512 + z
        unsigned o = (row & 511u) * 256u + (row >> 9);
        atomicAdd(out + lane * OUT_PLANE + o, v);
    }
}

// --- main SpMM: each warp owns a contiguous, sorted nnz chunk ------------------
__global__ void __launch_bounds__(256)
k_spmm(const float* __restrict__ vals,
       const unsigned* __restrict__ rows_u32,
       const unsigned* __restrict__ cols_u32,
       float* __restrict__ out) {
    const unsigned warp_id = (blockIdx.x * blockDim.x + threadIdx.x) >> 5;
    const unsigned lane    = threadIdx.x & 31u;
    const unsigned st      = g_stride;          // 1 (int32) or 2 (int64, read low word)
    const unsigned base    = warp_id * NNZ_PER_WARP;

    unsigned cur_row = rows_u32[st * base];     // first row of this chunk (broadcast load)
    float a0 = 0.f, a1 = 0.f, a2 = 0.f, a3 = 0.f;

    unsigned i = base + lane;
    #pragma unroll 1
    for (int it = 0; it < ITERS; ++it, i += 32u) {
        float    v   = vals[i];
        unsigned row = rows_u32[st * i];
        unsigned col = cols_u32[st * i];
        float4   r   = g_rhs[col];
        float c0 = v * r.x, c1 = v * r.y, c2 = v * r.z, c3 = v * r.w;

        // rows sorted => group uniform iff first == last
        unsigned r0  = __shfl_sync(0xffffffffu, row, 0);
        unsigned r31 = __shfl_sync(0xffffffffu, row, 31);

        if (r0 == r31) {
            if (r0 == cur_row) {                 // fast path (~75% + long rows)
                a0 += c0; a1 += c1; a2 += c2; a3 += c3;
            } else {                             // clean row switch at group boundary
                flush_row(cur_row, a0, a1, a2, a3, out);
                cur_row = r0;
                a0 = c0; a1 = c1; a2 = c2; a3 = c3;
            }
        } else {                                 // mixed group (row boundary inside)
            bool mine = (row == cur_row);        // prefix lanes still on cur_row (sorted)
            if (mine) { a0 += c0; a1 += c1; a2 += c2; a3 += c3; }
            flush_row(cur_row, a0, a1, a2, a3, out);
            if (!mine && row != r31) {
                // complete middle segment entirely inside this group (rare: needs a
                // row with <32 nnz) -> direct atomics, always correct
                unsigned o = (row & 511u) * 256u + (row >> 9);
                atomicAdd(out + o,                  c0);
                atomicAdd(out + OUT_PLANE + o,      c1);
                atomicAdd(out + 2u * OUT_PLANE + o, c2);
                atomicAdd(out + 3u * OUT_PLANE + o, c3);
            }
            bool last = (row == r31);            // suffix lanes start the new row
            a0 = last ? c0 : 0.f;
            a1 = last ? c1 : 0.f;
            a2 = last ? c2 : 0.f;
            a3 = last ? c3 : 0.f;
            cur_row = r31;
        }
    }
    flush_row(cur_row, a0, a1, a2, a3, out);
}

extern "C" void kernel_launch(void* const* d_in, const int* in_sizes, int n_in,
                              void* d_out, int out_size) {
    const float*    x    = (const float*)d_in[0];
    const float*    vals = (const float*)d_in[1];
    const unsigned* rows = (const unsigned*)d_in[2];
    const unsigned* cols = (const unsigned*)d_in[3];
    float*          out  = (float*)d_out;

    k_config   <<<1, 1>>>(rows);
    k_zero     <<<524288 / 256, 256>>>(out);
    k_build_rhs<<<NCOLS / 256, 256>>>(x);
    k_spmm     <<<TOTAL_WARPS * 32 / 256, 256>>>(vals, rows, cols, out);
}

// round 3
// speedup vs baseline: 1.0485x; 1.0485x over previous
#include <cuda_runtime.h>

// Fixed problem constants:
//   x: (4,1,128,2048) f32 ; vals: 16.7M f32 ; rows/cols: 16.7M int32-or-int64 (rows sorted)
//   out: (4,1,512,256) f32 = 524288 elements
#define NNZ_TOTAL   16777216
#define NCOLS       262144      // NS*NC = 2048*128
#define OUT_ELEMS   524288
#define OUT_PLANE   131072      // per-bk output plane (Nz*Nx)
#define TOTAL_WARPS 8192
#define NNZ_PER_WARP (NNZ_TOTAL / TOTAL_WARPS)   // 2048
#define ITERS        (NNZ_PER_WARP / 32)         // 64

// Scratch: transposed RHS, rhs_t[col] = {x[0,c,s], x[1,c,s], x[2,c,s], x[3,c,s]}, col = s*128 + c
static __device__ float4  g_rhs[NCOLS];          // 4 MB, L2-resident during main kernel
static __device__ unsigned g_stride;             // 2 if indices are int64, 1 if int32

// --- fused prep: dtype probe + zero output + build transposed RHS -------------
// dtype probe: word [NNZ-1] (u32 view) is in-bounds for both layouts:
//   int64: HIGH half of element (NNZ-2)/2 -> always 0 ; int32: last sorted row != 0
__global__ void k_prep(const float* __restrict__ x,
                       const unsigned* __restrict__ rows_u32,
                       float* __restrict__ out) {
    unsigned gid = blockIdx.x * blockDim.x + threadIdx.x;   // < 524288
    if (gid == 0) g_stride = (rows_u32[NNZ_TOTAL - 1] == 0u) ? 2u : 1u;
    out[gid] = 0.0f;                                        // d_out is poisoned 0xAA
    if (gid < NCOLS) {
        unsigned c = gid & 127u;
        unsigned s = gid >> 7;
        unsigned o = c * 2048u + s;
        float4 v;
        v.x = x[o];
        v.y = x[o + 262144u];
        v.z = x[o + 524288u];
        v.w = x[o + 786432u];
        g_rhs[gid] = v;
    }
}

// --- flush one completed row: butterfly reduce + 4 atomics (cold path) ---------
__device__ __forceinline__ void flush_row(unsigned row,
                                          float a0, float a1, float a2, float a3,
                                          unsigned lane,
                                          float* __restrict__ out) {
    #pragma unroll
    for (int d = 16; d > 0; d >>= 1) {
        a0 += __shfl_xor_sync(0xffffffffu, a0, d);
        a1 += __shfl_xor_sync(0xffffffffu, a1, d);
        a2 += __shfl_xor_sync(0xffffffffu, a2, d);
        a3 += __shfl_xor_sync(0xffffffffu, a3, d);
    }
    if (lane < 4u) {
        float s = (lane == 0u) ? a0 : (lane == 1u) ? a1 : (lane == 2u) ? a2 : a3;
        // out layout: bk*131072 + z*256 + x, with row r = x*512 + z
        unsigned o = (row & 511u) * 256u + (row >> 9);
        atomicAdd(out + lane * OUT_PLANE + o, s);
    }
}

// --- main SpMM: each warp owns a contiguous, sorted nnz chunk ------------------
__global__ void __launch_bounds__(256)
k_spmm(const float* __restrict__ vals,
       const unsigned* __restrict__ rows_u32,
       const unsigned* __restrict__ cols_u32,
       float* __restrict__ out) {
    const unsigned warp_id = (blockIdx.x * blockDim.x + threadIdx.x) >> 5;
    const unsigned lane    = threadIdx.x & 31u;
    const unsigned st      = g_stride;          // 1 (int32) or 2 (int64, read low word)
    const unsigned base    = warp_id * NNZ_PER_WARP;
    const unsigned rstep   = st * 32u;

    const float*    vp = vals     + base + lane;
    const unsigned* rp = rows_u32 + st * (base + lane);
    const unsigned* cp = cols_u32 + st * (base + lane);

    // pipeline stage 0
    float    v   = *vp;
    unsigned row = *rp;
    unsigned col = *cp;
    float4   r   = g_rhs[col];

    unsigned cur_row = __shfl_sync(0xffffffffu, row, 0);
    float a0 = 0.f, a1 = 0.f, a2 = 0.f, a3 = 0.f;

    #pragma unroll 1
    for (int it = 0; it < ITERS - 1; ++it) {
        // prefetch next iteration (hides gather latency behind the logic below)
        vp += 32u; rp += rstep; cp += rstep;
        float    vn   = *vp;
        unsigned rown = *rp;
        unsigned coln = *cp;
        float4   rn   = g_rhs[coln];

        float c0 = v * r.x, c1 = v * r.y, c2 = v * r.z, c3 = v * r.w;
        if (__all_sync(0xffffffffu, row == cur_row)) {       // fast path (~75%)
            a0 += c0; a1 += c1; a2 += c2; a3 += c3;
        } else {                                             // row boundary in group
            unsigned r31 = __shfl_sync(0xffffffffu, row, 31);
            bool mine = (row == cur_row);                    // sorted -> prefix lanes
            if (mine) { a0 += c0; a1 += c1; a2 += c2; a3 += c3; }
            flush_row(cur_row, a0, a1, a2, a3, lane, out);
            if (!mine && row != r31) {
                // row fully contained inside this group (needs <32 nnz): direct atomics
                unsigned o = (row & 511u) * 256u + (row >> 9);
                atomicAdd(out + o,                  c0);
                atomicAdd(out + OUT_PLANE + o,      c1);
                atomicAdd(out + 2u * OUT_PLANE + o, c2);
                atomicAdd(out + 3u * OUT_PLANE + o, c3);
            }
            bool last = (row == r31);                        // suffix lanes: new row
            a0 = last ? c0 : 0.f;
            a1 = last ? c1 : 0.f;
            a2 = last ? c2 : 0.f;
            a3 = last ? c3 : 0.f;
            cur_row = r31;
        }
        v = vn; row = rown; r = rn;
    }

    // epilogue: process final group
    {
        float c0 = v * r.x, c1 = v * r.y, c2 = v * r.z, c3 = v * r.w;
        if (__all_sync(0xffffffffu, row == cur_row)) {
            a0 += c0; a1 += c1; a2 += c2; a3 += c3;
        } else {
            unsigned r31 = __shfl_sync(0xffffffffu, row, 31);
            bool mine = (row == cur_row);
            if (mine) { a0 += c0; a1 += c1; a2 += c2; a3 += c3; }
            flush_row(cur_row, a0, a1, a2, a3, lane, out);
            if (!mine && row != r31) {
                unsigned o = (row & 511u) * 256u + (row >> 9);
                atomicAdd(out + o,                  c0);
                atomicAdd(out + OUT_PLANE + o,      c1);
                atomicAdd(out + 2u * OUT_PLANE + o, c2);
                atomicAdd(out + 3u * OUT_PLANE + o, c3);
            }
            bool last = (row == r31);
            a0 = last ? c0 : 0.f;
            a1 = last ? c1 : 0.f;
            a2 = last ? c2 : 0.f;
            a3 = last ? c3 : 0.f;
            cur_row = r31;
        }
    }
    flush_row(cur_row, a0, a1, a2, a3, lane, out);
}

extern "C" void kernel_launch(void* const* d_in, const int* in_sizes, int n_in,
                              void* d_out, int out_size) {
    const float*    x    = (const float*)d_in[0];
    const float*    vals = (const float*)d_in[1];
    const unsigned* rows = (const unsigned*)d_in[2];
    const unsigned* cols = (const unsigned*)d_in[3];
    float*          out  = (float*)d_out;

    k_prep<<<OUT_ELEMS / 256, 256>>>(x, rows, out);
    k_spmm<<<TOTAL_WARPS * 32 / 256, 256>>>(vals, rows, cols, out);
}